// round 1
// baseline (speedup 1.0000x reference)
#include <cuda_runtime.h>
#include <stdint.h>

#define B_MAX 16384

// ---------------- scratch (device globals; no allocation) ----------------
__device__ unsigned g_xbits[B_MAX * 32];          // [b][y] 32 sign bits per row
__device__ unsigned g_c1bits[B_MAX * 6 * 14];     // [b][oc][py] 14-bit rows after conv1+pool+binarize
__device__ unsigned g_s2pos[B_MAX * 16];          // [b][oc] 25-bit pos plane after conv2+pool
__device__ unsigned g_s2msk[B_MAX * 16];          // [b][oc] 25-bit nonzero-mask plane
__device__ unsigned g_wp1[6];                     // conv1 weight sign bits (25 per oc)
__device__ unsigned g_wp2[16 * 6];                // conv2 weight sign bits (25 per (oc,ic))
__device__ unsigned g_fw1[120 * 16];              // fc1 weights: 25-bit word per (n, oc)
__device__ unsigned g_fw2[84 * 4];                // fc2 weights: 120 bits -> 4 words per n
__device__ unsigned g_fw3[10 * 3];                // fc3 weights: 84 bits -> 3 words per n

// ---------------- K0: pack all weights into sign bitmasks ----------------
__global__ void pack_weights(const float* __restrict__ w1, const float* __restrict__ w2,
                             const float* __restrict__ f1, const float* __restrict__ f2,
                             const float* __restrict__ f3) {
    int t = blockIdx.x * blockDim.x + threadIdx.x;
    int stride = blockDim.x * gridDim.x;

    if (t < 6) {
        unsigned v = 0;
        for (int i = 0; i < 25; i++) v |= (unsigned)(w1[t * 25 + i] > 0.f) << i;
        g_wp1[t] = v;
    }
    if (t < 96) {  // t = oc*6 + ic
        unsigned v = 0;
        for (int i = 0; i < 25; i++) v |= (unsigned)(w2[t * 25 + i] > 0.f) << i;
        g_wp2[t] = v;
    }
    for (int w = t; w < 120 * 16; w += stride) {   // (n, oc) -> 25 bits
        int n = w >> 4, oc = w & 15;
        unsigned v = 0;
        for (int i = 0; i < 25; i++) v |= (unsigned)(f1[n * 400 + oc * 25 + i] > 0.f) << i;
        g_fw1[w] = v;
    }
    for (int w = t; w < 84 * 4; w += stride) {     // (n, j) -> bits j*32+k of 120
        int n = w >> 2, j = w & 3;
        unsigned v = 0;
        for (int k = 0; k < 32; k++) {
            int i = j * 32 + k;
            if (i < 120) v |= (unsigned)(f2[n * 120 + i] > 0.f) << k;
        }
        g_fw2[w] = v;
    }
    for (int w = t; w < 10 * 3; w += stride) {     // (n, j) -> bits j*32+k of 84
        int n = w / 3, j = w % 3;
        unsigned v = 0;
        for (int k = 0; k < 32; k++) {
            int i = j * 32 + k;
            if (i < 84) v |= (unsigned)(f3[n * 84 + i] > 0.f) << k;
        }
        g_fw3[w] = v;
    }
}

// ---------------- K1: ballot-pack x signs, one warp per 32-pixel row -----
__global__ void pack_x(const float* __restrict__ x, int nrows) {
    int t = blockIdx.x * blockDim.x + threadIdx.x;
    int row = t >> 5;
    int lane = t & 31;
    if (row >= nrows) return;
    float v = x[row * 32 + lane];
    unsigned bits = __ballot_sync(0xffffffffu, v > 0.f);
    if (lane == 0) g_xbits[row] = bits;
}

// ---------------- K2: conv1 + maxpool + binarize (fused) -----------------
// dot = 25 - 2*popc(win ^ w) ; >0 <=> popc <= 12 ; conv1 outputs are odd => never 0
// pooled sign bit = OR over the 2x2 window of the per-position sign bit.
__global__ void conv1_k(int B) {
    int t = blockIdx.x * blockDim.x + threadIdx.x;
    if (t >= B * 14) return;
    int b = t / 14, py = t % 14;

    unsigned r[6];
#pragma unroll
    for (int k = 0; k < 6; k++) r[k] = g_xbits[b * 32 + 2 * py + k];
    unsigned w[6];
#pragma unroll
    for (int oc = 0; oc < 6; oc++) w[oc] = g_wp1[oc];

    unsigned out0 = 0, out1 = 0, out2 = 0, out3 = 0, out4 = 0, out5 = 0;
#pragma unroll
    for (int cr = 0; cr < 2; cr++) {
#pragma unroll
        for (int ox = 0; ox < 28; ox++) {
            unsigned win = 0;
#pragma unroll
            for (int j = 0; j < 5; j++) win |= ((r[cr + j] >> ox) & 31u) << (5 * j);
            unsigned bit = 1u << (ox >> 1);
            if (__popc(win ^ w[0]) <= 12) out0 |= bit;
            if (__popc(win ^ w[1]) <= 12) out1 |= bit;
            if (__popc(win ^ w[2]) <= 12) out2 |= bit;
            if (__popc(win ^ w[3]) <= 12) out3 |= bit;
            if (__popc(win ^ w[4]) <= 12) out4 |= bit;
            if (__popc(win ^ w[5]) <= 12) out5 |= bit;
        }
    }
    unsigned* dst = &g_c1bits[b * 6 * 14 + py];
    dst[0 * 14] = out0; dst[1 * 14] = out1; dst[2 * 14] = out2;
    dst[3 * 14] = out3; dst[4 * 14] = out4; dst[5 * 14] = out5;
}

// ---------------- K2b: clear s2 planes (atomicOr targets) ----------------
__global__ void clear_s2(int n) {
    int t = blockIdx.x * blockDim.x + threadIdx.x;
    if (t < n) { g_s2pos[t] = 0u; g_s2msk[t] = 0u; }
}

// ---------------- K3: conv2 + maxpool + ternarize (fused) ----------------
// dot = 150 - 2*d ; +1 <=> d<=74 ; ==0 <=> d==75. Pooled: pos = any(d<=74);
// zero = !pos && any(d==75); mask = !zero.
__global__ void conv2_k(int B) {
    __shared__ unsigned sw2[96];
    for (int i = threadIdx.x; i < 96; i += blockDim.x) sw2[i] = g_wp2[i];
    __syncthreads();

    int t = blockIdx.x * blockDim.x + threadIdx.x;
    if (t >= B * 5) return;
    int b = t / 5, py = t % 5;

    unsigned rows[6][6];  // [ic][k] input rows 2*py .. 2*py+5
#pragma unroll
    for (int ic = 0; ic < 6; ic++)
#pragma unroll
        for (int k = 0; k < 6; k++)
            rows[ic][k] = g_c1bits[(b * 6 + ic) * 14 + 2 * py + k];

    unsigned posm[16], eqm[16];
#pragma unroll
    for (int oc = 0; oc < 16; oc++) { posm[oc] = 0u; eqm[oc] = 0u; }

#pragma unroll
    for (int cr = 0; cr < 2; cr++) {
#pragma unroll
        for (int ox = 0; ox < 10; ox++) {
            unsigned win[6];
#pragma unroll
            for (int ic = 0; ic < 6; ic++) {
                unsigned wv = 0;
#pragma unroll
                for (int j = 0; j < 5; j++)
                    wv |= ((rows[ic][cr + j] >> ox) & 31u) << (5 * j);
                win[ic] = wv;
            }
            unsigned pbit = 1u << (ox >> 1);
#pragma unroll
            for (int oc = 0; oc < 16; oc++) {
                int d = 0;
#pragma unroll
                for (int ic = 0; ic < 6; ic++)
                    d += __popc(win[ic] ^ sw2[oc * 6 + ic]);
                if (d <= 74) posm[oc] |= pbit;
                if (d == 75) eqm[oc] |= pbit;
            }
        }
    }
#pragma unroll
    for (int oc = 0; oc < 16; oc++) {
        unsigned zm = (~posm[oc]) & eqm[oc] & 31u;   // zero cells
        unsigned mm = (~zm) & 31u;                   // nonzero mask
        atomicOr(&g_s2pos[b * 16 + oc], posm[oc] << (5 * py));
        atomicOr(&g_s2msk[b * 16 + oc], mm << (5 * py));
    }
}

// ---------------- K4: fc1 -> fc2 -> fc3 fused, one warp per image --------
__global__ void fc_k(float* __restrict__ out, int B) {
    int warp = (blockIdx.x * blockDim.x + threadIdx.x) >> 5;
    int lane = threadIdx.x & 31;
    if (warp >= B) return;
    int b = warp;

    unsigned sp[16], sm[16];
#pragma unroll
    for (int i = 0; i < 16; i++) { sp[i] = g_s2pos[b * 16 + i]; sm[i] = g_s2msk[b * 16 + i]; }
    int M1 = 0;
#pragma unroll
    for (int i = 0; i < 16; i++) M1 += __popc(sm[i]);

    // fc1: 120 neurons; neuron n = k*32 + lane
    unsigned p2s[4], p2m[4];
#pragma unroll
    for (int k = 0; k < 4; k++) {
        int n = k * 32 + lane;
        int v = 0;
        bool valid = (n < 120);
        if (valid) {
            int p = 0;
#pragma unroll
            for (int i = 0; i < 16; i++)
                p += __popc(~(sp[i] ^ g_fw1[n * 16 + i]) & sm[i]);
            v = 2 * p - M1;
        }
        p2s[k] = __ballot_sync(0xffffffffu, valid && (v > 0));
        p2m[k] = __ballot_sync(0xffffffffu, valid && (v != 0));
    }
    int M2 = __popc(p2m[0]) + __popc(p2m[1]) + __popc(p2m[2]) + __popc(p2m[3]);

    // fc2: 84 neurons
    unsigned p3s[3], p3m[3];
#pragma unroll
    for (int k = 0; k < 3; k++) {
        int n = k * 32 + lane;
        int v = 0;
        bool valid = (n < 84);
        if (valid) {
            int p = 0;
#pragma unroll
            for (int j = 0; j < 4; j++)
                p += __popc(~(p2s[j] ^ g_fw2[n * 4 + j]) & p2m[j]);
            v = 2 * p - M2;
        }
        p3s[k] = __ballot_sync(0xffffffffu, valid && (v > 0));
        p3m[k] = __ballot_sync(0xffffffffu, valid && (v != 0));
    }
    int M3 = __popc(p3m[0]) + __popc(p3m[1]) + __popc(p3m[2]);

    // fc3: 10 neurons, raw integer value as float output
    if (lane < 10) {
        int p = 0;
#pragma unroll
        for (int j = 0; j < 3; j++)
            p += __popc(~(p3s[j] ^ g_fw3[lane * 3 + j]) & p3m[j]);
        out[b * 10 + lane] = (float)(2 * p - M3);
    }
}

// ---------------- launch ----------------
extern "C" void kernel_launch(void* const* d_in, const int* in_sizes, int n_in,
                              void* d_out, int out_size) {
    const float* x  = (const float*)d_in[0];
    const float* w1 = (const float*)d_in[1];
    const float* w2 = (const float*)d_in[2];
    const float* f1 = (const float*)d_in[3];
    const float* f2 = (const float*)d_in[4];
    const float* f3 = (const float*)d_in[5];
    float* out = (float*)d_out;

    int B = in_sizes[0] / 1024;
    if (B > B_MAX) B = B_MAX;

    pack_weights<<<8, 256>>>(w1, w2, f1, f2, f3);

    int nrows = B * 32;
    pack_x<<<(nrows * 32 + 255) / 256, 256>>>(x, nrows);

    clear_s2<<<(B * 16 + 255) / 256, 256>>>(B * 16);

    conv1_k<<<(B * 14 + 255) / 256, 256>>>(B);

    conv2_k<<<(B * 5 + 255) / 256, 256>>>(B);

    fc_k<<<(B + 7) / 8, 256>>>(out, B);
}

// round 2
// speedup vs baseline: 1.5234x; 1.5234x over previous
#include <cuda_runtime.h>
#include <stdint.h>

#define B_MAX 16384

// ---------------- scratch (device globals; no allocation) ----------------
__device__ unsigned g_xbits[B_MAX * 32];           // [b][y] 32 sign bits per row
__device__ unsigned g_c1bits[B_MAX * 14 * 6];      // [b][row][ic] 14-bit rows after conv1+pool
__device__ unsigned g_s2[B_MAX * 5 * 16];          // [b][py][oc]: posm(5b) | mask(5b)<<8
__device__ unsigned g_wp1[6];                      // conv1 weight sign bits (25 per oc)
__device__ unsigned g_wp2[16 * 8];                 // conv2 weight bits, padded to 8 per oc
__device__ unsigned g_fw1[120 * 16];               // fc1: 25-bit word per (n, oc)
__device__ unsigned g_fw2[84 * 4];                 // fc2: 120 bits -> 4 words per n
__device__ unsigned g_fw3[10 * 3];                 // fc3: 84 bits -> 3 words per n

// ---------------- K0: pack all weights into sign bitmasks ----------------
__global__ void pack_weights(const float* __restrict__ w1, const float* __restrict__ w2,
                             const float* __restrict__ f1, const float* __restrict__ f2,
                             const float* __restrict__ f3) {
    int t = blockIdx.x * blockDim.x + threadIdx.x;
    int stride = blockDim.x * gridDim.x;

    if (t < 6) {
        unsigned v = 0;
        for (int i = 0; i < 25; i++) v |= (unsigned)(w1[t * 25 + i] > 0.f) << i;
        g_wp1[t] = v;
    }
    if (t < 128) {  // t = oc*8 + ic, padded
        int oc = t >> 3, ic = t & 7;
        unsigned v = 0;
        if (ic < 6)
            for (int i = 0; i < 25; i++) v |= (unsigned)(w2[(oc * 6 + ic) * 25 + i] > 0.f) << i;
        g_wp2[t] = v;
    }
    for (int w = t; w < 120 * 16; w += stride) {   // (n, oc) -> 25 bits
        int n = w >> 4, oc = w & 15;
        unsigned v = 0;
        for (int i = 0; i < 25; i++) v |= (unsigned)(f1[n * 400 + oc * 25 + i] > 0.f) << i;
        g_fw1[w] = v;
    }
    for (int w = t; w < 84 * 4; w += stride) {     // (n, j) -> bits j*32+k of 120
        int n = w >> 2, j = w & 3;
        unsigned v = 0;
        for (int k = 0; k < 32; k++) {
            int i = j * 32 + k;
            if (i < 120) v |= (unsigned)(f2[n * 120 + i] > 0.f) << k;
        }
        g_fw2[w] = v;
    }
    for (int w = t; w < 10 * 3; w += stride) {     // (n, j) -> bits j*32+k of 84
        int n = w / 3, j = w % 3;
        unsigned v = 0;
        for (int k = 0; k < 32; k++) {
            int i = j * 32 + k;
            if (i < 84) v |= (unsigned)(f3[n * 84 + i] > 0.f) << k;
        }
        g_fw3[w] = v;
    }
}

// ---------------- K1: ballot-pack x signs, one warp per 32-pixel row -----
__global__ void pack_x(const float* __restrict__ x, int nrows) {
    int t = blockIdx.x * blockDim.x + threadIdx.x;
    int row = t >> 5;
    int lane = t & 31;
    if (row >= nrows) return;
    float v = x[row * 32 + lane];
    unsigned bits = __ballot_sync(0xffffffffu, v > 0.f);
    if (lane == 0) g_xbits[row] = bits;
}

// ---------------- K2: conv1 + maxpool + binarize (fused) -----------------
// dot = 25 - 2*popc(win ^ w) ; >0 <=> popc <= 12 ; conv1 outputs odd => never 0
__global__ void conv1_k(int B) {
    int t = blockIdx.x * blockDim.x + threadIdx.x;
    if (t >= B * 14) return;
    int b = t / 14, py = t % 14;

    unsigned r[6];
#pragma unroll
    for (int k = 0; k < 6; k++) r[k] = g_xbits[b * 32 + 2 * py + k];
    unsigned w[6];
#pragma unroll
    for (int oc = 0; oc < 6; oc++) w[oc] = g_wp1[oc];

    unsigned out0 = 0, out1 = 0, out2 = 0, out3 = 0, out4 = 0, out5 = 0;
#pragma unroll
    for (int cr = 0; cr < 2; cr++) {
#pragma unroll
        for (int ox = 0; ox < 28; ox++) {
            unsigned win = 0;
#pragma unroll
            for (int j = 0; j < 5; j++) win |= ((r[cr + j] >> ox) & 31u) << (5 * j);
            unsigned bit = 1u << (ox >> 1);
            if (__popc(win ^ w[0]) <= 12) out0 |= bit;
            if (__popc(win ^ w[1]) <= 12) out1 |= bit;
            if (__popc(win ^ w[2]) <= 12) out2 |= bit;
            if (__popc(win ^ w[3]) <= 12) out3 |= bit;
            if (__popc(win ^ w[4]) <= 12) out4 |= bit;
            if (__popc(win ^ w[5]) <= 12) out5 |= bit;
        }
    }
    // layout [b][row][ic]: 6 consecutive words, 8B-aligned -> 3x STG.64
    uint2* dst = (uint2*)&g_c1bits[(b * 14 + py) * 6];
    dst[0] = make_uint2(out0, out1);
    dst[1] = make_uint2(out2, out3);
    dst[2] = make_uint2(out4, out5);
}

// ---------------- K3: conv2 + maxpool + ternarize (fused) ----------------
// dot = 150 - 2*d ; +1 <=> d<=74 ; ==0 <=> d==75
__global__ void conv2_k(int B) {
    __shared__ uint4 sw[16][2];
    if (threadIdx.x < 32) {
        int oc = threadIdx.x >> 1, h = threadIdx.x & 1;
        const uint4* src = (const uint4*)&g_wp2[oc * 8];
        sw[oc][h] = src[h];
    }
    __syncthreads();

    int t = blockIdx.x * blockDim.x + threadIdx.x;
    if (t >= B * 5) return;
    int b = t / 5, py = t % 5;

    unsigned rows[6][6];  // [ic][k] input rows 2*py .. 2*py+5
#pragma unroll
    for (int k = 0; k < 6; k++) {
        const uint2* p = (const uint2*)&g_c1bits[(b * 14 + 2 * py + k) * 6];
        uint2 a = p[0], c = p[1], d = p[2];
        rows[0][k] = a.x; rows[1][k] = a.y;
        rows[2][k] = c.x; rows[3][k] = c.y;
        rows[4][k] = d.x; rows[5][k] = d.y;
    }

    // flags[oc]: bits 0-4 = pos (any d<=74 in 2x2), bits 8-12 = eq (any d==75)
    unsigned flags[16];
#pragma unroll
    for (int oc = 0; oc < 16; oc++) flags[oc] = 0u;

#pragma unroll
    for (int cr = 0; cr < 2; cr++) {
#pragma unroll
        for (int ox = 0; ox < 10; ox++) {
            unsigned win[6];
#pragma unroll
            for (int ic = 0; ic < 6; ic++) {
                unsigned wv = 0;
#pragma unroll
                for (int j = 0; j < 5; j++)
                    wv |= ((rows[ic][cr + j] >> ox) & 31u) << (5 * j);
                win[ic] = wv;
            }
            unsigned pbit = 1u << (ox >> 1);
#pragma unroll
            for (int oc = 0; oc < 16; oc++) {
                uint4 wa = sw[oc][0];
                uint4 wb = sw[oc][1];
                int d = __popc(win[0] ^ wa.x) + __popc(win[1] ^ wa.y)
                      + __popc(win[2] ^ wa.z) + __popc(win[3] ^ wa.w)
                      + __popc(win[4] ^ wb.x) + __popc(win[5] ^ wb.y);
                if (d <= 74) flags[oc] |= pbit;
                if (d == 75) flags[oc] |= (pbit << 8);
            }
        }
    }

    unsigned res[16];
#pragma unroll
    for (int oc = 0; oc < 16; oc++) {
        unsigned posm = flags[oc] & 31u;
        unsigned eqm = (flags[oc] >> 8) & 31u;
        unsigned zm = (~posm) & eqm & 31u;   // zero cells
        unsigned mm = (~zm) & 31u;           // nonzero mask
        res[oc] = posm | (mm << 8);
    }
    uint4* dst = (uint4*)&g_s2[(b * 5 + py) * 16];
#pragma unroll
    for (int h = 0; h < 4; h++)
        dst[h] = make_uint4(res[h * 4], res[h * 4 + 1], res[h * 4 + 2], res[h * 4 + 3]);
}

// ---------------- K4: fc1 -> fc2 -> fc3 fused, one warp per image --------
__global__ void fc_k(float* __restrict__ out, int B) {
    // padded shared weights: odd strides -> conflict-free LDS
    __shared__ unsigned s1[120 * 17];
    __shared__ unsigned s2w[84 * 5];
    __shared__ unsigned s3w[30];
    int tid = threadIdx.x;
    for (int i = tid; i < 120 * 16; i += 256) s1[(i >> 4) * 17 + (i & 15)] = g_fw1[i];
    for (int i = tid; i < 84 * 4; i += 256) s2w[(i >> 2) * 5 + (i & 3)] = g_fw2[i];
    if (tid < 30) s3w[tid] = g_fw3[tid];
    __syncthreads();

    int warp = blockIdx.x * 8 + (tid >> 5);
    int lane = tid & 31;
    if (warp >= B) return;
    int b = warp;

    // assemble ternary bitplanes from conv2 output (uniform broadcast loads)
    unsigned sp[16], sm[16];
#pragma unroll
    for (int oc = 0; oc < 16; oc++) { sp[oc] = 0u; sm[oc] = 0u; }
#pragma unroll
    for (int py = 0; py < 5; py++) {
        const uint4* q = (const uint4*)&g_s2[(b * 5 + py) * 16];
#pragma unroll
        for (int h = 0; h < 4; h++) {
            uint4 v = q[h];
            unsigned vv[4] = {v.x, v.y, v.z, v.w};
#pragma unroll
            for (int m = 0; m < 4; m++) {
                sp[h * 4 + m] |= (vv[m] & 31u) << (5 * py);
                sm[h * 4 + m] |= ((vv[m] >> 8) & 31u) << (5 * py);
            }
        }
    }
    int M1 = 0;
#pragma unroll
    for (int i = 0; i < 16; i++) M1 += __popc(sm[i]);

    // fc1: 120 neurons; neuron n = k*32 + lane
    unsigned p2s[4], p2m[4];
#pragma unroll
    for (int k = 0; k < 4; k++) {
        int n = k * 32 + lane;
        int v = 0;
        bool valid = (n < 120);
        if (valid) {
            int p = 0;
#pragma unroll
            for (int i = 0; i < 16; i++)
                p += __popc((~(sp[i] ^ s1[n * 17 + i])) & sm[i]);
            v = 2 * p - M1;
        }
        p2s[k] = __ballot_sync(0xffffffffu, valid && (v > 0));
        p2m[k] = __ballot_sync(0xffffffffu, valid && (v != 0));
    }
    int M2 = __popc(p2m[0]) + __popc(p2m[1]) + __popc(p2m[2]) + __popc(p2m[3]);

    // fc2: 84 neurons
    unsigned p3s[3], p3m[3];
#pragma unroll
    for (int k = 0; k < 3; k++) {
        int n = k * 32 + lane;
        int v = 0;
        bool valid = (n < 84);
        if (valid) {
            int p = 0;
#pragma unroll
            for (int j = 0; j < 4; j++)
                p += __popc((~(p2s[j] ^ s2w[n * 5 + j])) & p2m[j]);
            v = 2 * p - M2;
        }
        p3s[k] = __ballot_sync(0xffffffffu, valid && (v > 0));
        p3m[k] = __ballot_sync(0xffffffffu, valid && (v != 0));
    }
    int M3 = __popc(p3m[0]) + __popc(p3m[1]) + __popc(p3m[2]);

    // fc3: 10 neurons
    if (lane < 10) {
        int p = 0;
#pragma unroll
        for (int j = 0; j < 3; j++)
            p += __popc((~(p3s[j] ^ s3w[lane * 3 + j])) & p3m[j]);
        out[b * 10 + lane] = (float)(2 * p - M3);
    }
}

// ---------------- launch ----------------
extern "C" void kernel_launch(void* const* d_in, const int* in_sizes, int n_in,
                              void* d_out, int out_size) {
    const float* x  = (const float*)d_in[0];
    const float* w1 = (const float*)d_in[1];
    const float* w2 = (const float*)d_in[2];
    const float* f1 = (const float*)d_in[3];
    const float* f2 = (const float*)d_in[4];
    const float* f3 = (const float*)d_in[5];
    float* out = (float*)d_out;

    int B = in_sizes[0] / 1024;
    if (B > B_MAX) B = B_MAX;

    pack_weights<<<8, 256>>>(w1, w2, f1, f2, f3);

    int nrows = B * 32;
    pack_x<<<(nrows * 32 + 255) / 256, 256>>>(x, nrows);

    conv1_k<<<(B * 14 + 255) / 256, 256>>>(B);

    conv2_k<<<(B * 5 + 255) / 256, 256>>>(B);

    fc_k<<<(B + 7) / 8, 256>>>(out, B);
}

// round 3
// speedup vs baseline: 2.0103x; 1.3196x over previous
#include <cuda_runtime.h>
#include <stdint.h>

#define B_MAX 16384

// ---------------- scratch (device globals; no allocation) ----------------
__device__ unsigned g_xbits[B_MAX * 32];           // [b][y] 32 sign bits per row
__device__ unsigned g_c1bits[B_MAX * 14 * 6];      // [b][row][ic] 14-bit rows after conv1+pool
__device__ unsigned g_s2[B_MAX * 25];              // [b][cell]: pos bits 0-15, mask bits 16-31
__device__ unsigned g_wp1[8];                      // conv1 weight sign bits (25 per oc), padded
__device__ unsigned g_wp2[16 * 8];                 // conv2 weights packed 150b -> 5 words, pad 8
__device__ unsigned g_fw1[120 * 16];               // fc1: 25-bit word per (n, oc)
__device__ unsigned g_fw2[84 * 4];                 // fc2: 120 bits -> 4 words per n
__device__ unsigned g_fw3[10 * 3];                 // fc3: 84 bits -> 3 words per n

// ---------------- K0: pack all weights into sign bitmasks ----------------
__global__ void pack_weights(const float* __restrict__ w1, const float* __restrict__ w2,
                             const float* __restrict__ f1, const float* __restrict__ f2,
                             const float* __restrict__ f3) {
    int t = blockIdx.x * blockDim.x + threadIdx.x;
    int stride = blockDim.x * gridDim.x;

    if (t < 8) {
        unsigned v = 0;
        if (t < 6)
            for (int i = 0; i < 25; i++) v |= (unsigned)(w1[t * 25 + i] > 0.f) << i;
        g_wp1[t] = v;
    }
    if (t < 16) {  // oc: pack 6x25 bits -> 5x32-bit dense words
        unsigned wi[6];
        for (int ic = 0; ic < 6; ic++) {
            unsigned v = 0;
            for (int i = 0; i < 25; i++) v |= (unsigned)(w2[(t * 6 + ic) * 25 + i] > 0.f) << i;
            wi[ic] = v;
        }
        g_wp2[t * 8 + 0] = wi[0] | (wi[1] << 25);
        g_wp2[t * 8 + 1] = (wi[1] >> 7) | (wi[2] << 18);
        g_wp2[t * 8 + 2] = (wi[2] >> 14) | (wi[3] << 11);
        g_wp2[t * 8 + 3] = (wi[3] >> 21) | (wi[4] << 4) | (wi[5] << 29);
        g_wp2[t * 8 + 4] = (wi[5] >> 3);
        g_wp2[t * 8 + 5] = 0; g_wp2[t * 8 + 6] = 0; g_wp2[t * 8 + 7] = 0;
    }
    for (int w = t; w < 120 * 16; w += stride) {   // (n, oc) -> 25 bits
        int n = w >> 4, oc = w & 15;
        unsigned v = 0;
        for (int i = 0; i < 25; i++) v |= (unsigned)(f1[n * 400 + oc * 25 + i] > 0.f) << i;
        g_fw1[w] = v;
    }
    for (int w = t; w < 84 * 4; w += stride) {     // (n, j) -> bits j*32+k of 120
        int n = w >> 2, j = w & 3;
        unsigned v = 0;
        for (int k = 0; k < 32; k++) {
            int i = j * 32 + k;
            if (i < 120) v |= (unsigned)(f2[n * 120 + i] > 0.f) << k;
        }
        g_fw2[w] = v;
    }
    for (int w = t; w < 10 * 3; w += stride) {     // (n, j) -> bits j*32+k of 84
        int n = w / 3, j = w % 3;
        unsigned v = 0;
        for (int k = 0; k < 32; k++) {
            int i = j * 32 + k;
            if (i < 84) v |= (unsigned)(f3[n * 84 + i] > 0.f) << k;
        }
        g_fw3[w] = v;
    }
}

// ---------------- K1: ballot-pack x signs, one warp per 32-pixel row -----
__global__ void pack_x(const float* __restrict__ x, int nrows) {
    int t = blockIdx.x * blockDim.x + threadIdx.x;
    int row = t >> 5;
    int lane = t & 31;
    if (row >= nrows) return;
    float v = x[row * 32 + lane];
    unsigned bits = __ballot_sync(0xffffffffu, v > 0.f);
    if (lane == 0) g_xbits[row] = bits;
}

// ---------------- K2: conv1 + maxpool + binarize (fused) -----------------
// dot = 25 - 2*popc ; >0 <=> popc <= 12 ; conv1 outputs odd => never 0
// pooled sign over 2x2 = (min of the 4 popcs) <= 12
__global__ void conv1_k(int B) {
    int t = blockIdx.x * blockDim.x + threadIdx.x;
    if (t >= B * 14) return;
    int b = t / 14, py = t % 14;

    unsigned r[6];
#pragma unroll
    for (int k = 0; k < 6; k++) r[k] = g_xbits[b * 32 + 2 * py + k];
    unsigned w[6];
#pragma unroll
    for (int oc = 0; oc < 6; oc++) w[oc] = g_wp1[oc];

    unsigned out[6] = {0, 0, 0, 0, 0, 0};
#pragma unroll
    for (int ox = 0; ox < 28; ox++) {
        unsigned win0 = 0;
#pragma unroll
        for (int j = 0; j < 5; j++) win0 |= ((r[j] >> ox) & 31u) << (5 * j);
        unsigned win1 = (win0 >> 5) | (((r[5] >> ox) & 31u) << 20);
        unsigned bit = 1u << (ox >> 1);
#pragma unroll
        for (int oc = 0; oc < 6; oc++) {
            int m = min(__popc(win0 ^ w[oc]), __popc(win1 ^ w[oc]));
            if (m <= 12) out[oc] |= bit;
        }
    }
    uint2* dst = (uint2*)&g_c1bits[(b * 14 + py) * 6];
    dst[0] = make_uint2(out[0], out[1]);
    dst[1] = make_uint2(out[2], out[3]);
    dst[2] = make_uint2(out[4], out[5]);
}

// ---------------- K3: conv2 + maxpool + ternarize (fused) ----------------
// thread = one pooled output cell (b, py, px), covers 2x2 conv windows x 16 oc
// dot = 150 - 2*d ; pooled>0 <=> min4(d)<=74 ; pooled==0 <=> min4(d)==75
__global__ void __launch_bounds__(256, 4) conv2_k(int B) {
    __shared__ uint4 sw4[16][2];
    if (threadIdx.x < 32) {
        int oc = threadIdx.x >> 1, h = threadIdx.x & 1;
        sw4[oc][h] = ((const uint4*)&g_wp2[oc * 8])[h];
    }
    __syncthreads();

    int t = blockIdx.x * blockDim.x + threadIdx.x;
    if (t >= B * 25) return;
    int b = t / 25;
    int cell = t % 25;
    int py = cell / 5, px = cell % 5;

    unsigned rows[6][6];  // [ic][k] c1 rows 2*py .. 2*py+5
#pragma unroll
    for (int k = 0; k < 6; k++) {
        const uint2* p = (const uint2*)&g_c1bits[(b * 14 + 2 * py + k) * 6];
        uint2 a = p[0], c = p[1], d = p[2];
        rows[0][k] = a.x; rows[1][k] = a.y;
        rows[2][k] = c.x; rows[3][k] = c.y;
        rows[4][k] = d.x; rows[5][k] = d.y;
    }

    // build 4 windows (2 ox, 2 cr), each packed 150 bits -> 5 words
    unsigned wpk[4][5];
#pragma unroll
    for (int h = 0; h < 2; h++) {       // ox = 2*px + h
        int ox = 2 * px + h;
        unsigned w0[6], w1[6];
#pragma unroll
        for (int ic = 0; ic < 6; ic++) {
            unsigned v = 0;
#pragma unroll
            for (int j = 0; j < 5; j++) v |= ((rows[ic][j] >> ox) & 31u) << (5 * j);
            w0[ic] = v;
            w1[ic] = (v >> 5) | (((rows[ic][5] >> ox) & 31u) << 20);
        }
        wpk[h][0] = w0[0] | (w0[1] << 25);
        wpk[h][1] = (w0[1] >> 7) | (w0[2] << 18);
        wpk[h][2] = (w0[2] >> 14) | (w0[3] << 11);
        wpk[h][3] = (w0[3] >> 21) | (w0[4] << 4) | (w0[5] << 29);
        wpk[h][4] = (w0[5] >> 3);
        wpk[2 + h][0] = w1[0] | (w1[1] << 25);
        wpk[2 + h][1] = (w1[1] >> 7) | (w1[2] << 18);
        wpk[2 + h][2] = (w1[2] >> 14) | (w1[3] << 11);
        wpk[2 + h][3] = (w1[3] >> 21) | (w1[4] << 4) | (w1[5] << 29);
        wpk[2 + h][4] = (w1[5] >> 3);
    }

    unsigned word = 0;
#pragma unroll
    for (int oc = 0; oc < 16; oc++) {
        uint4 wa = sw4[oc][0];
        uint4 wb = sw4[oc][1];
        int m = 1000;
#pragma unroll
        for (int q = 0; q < 4; q++) {
            int d = __popc(wpk[q][0] ^ wa.x) + __popc(wpk[q][1] ^ wa.y)
                  + __popc(wpk[q][2] ^ wa.z) + __popc(wpk[q][3] ^ wa.w)
                  + __popc(wpk[q][4] ^ wb.x);
            m = min(m, d);
        }
        if (m <= 74) word |= 1u << oc;          // pooled value > 0
        if (m != 75) word |= 1u << (16 + oc);   // pooled value != 0
    }
    g_s2[b * 25 + cell] = word;
}

// ---------------- K4: fc1 -> fc2 -> fc3 fused, one warp per image --------
__global__ void fc_k(float* __restrict__ out, int B) {
    // padded shared weights: odd strides -> conflict-free LDS
    __shared__ unsigned s1[120 * 17];
    __shared__ unsigned s2w[84 * 5];
    __shared__ unsigned s3w[30];
    int tid = threadIdx.x;
    for (int i = tid; i < 120 * 16; i += 256) s1[(i >> 4) * 17 + (i & 15)] = g_fw1[i];
    for (int i = tid; i < 84 * 4; i += 256) s2w[(i >> 2) * 5 + (i & 3)] = g_fw2[i];
    if (tid < 30) s3w[tid] = g_fw3[tid];
    __syncthreads();

    int warp = blockIdx.x * 8 + (tid >> 5);
    int lane = tid & 31;
    if (warp >= B) return;
    int b = warp;

    // assemble ternary bitplanes via ballots: lane = cell
    unsigned W = (lane < 25) ? g_s2[b * 25 + lane] : 0u;
    unsigned sp[16], sm[16];
#pragma unroll
    for (int oc = 0; oc < 16; oc++) {
        sp[oc] = __ballot_sync(0xffffffffu, (W >> oc) & 1u);
        sm[oc] = __ballot_sync(0xffffffffu, (W >> (16 + oc)) & 1u);
    }
    int M1 = 0;
#pragma unroll
    for (int i = 0; i < 16; i++) M1 += __popc(sm[i]);

    // fc1: 120 neurons; neuron n = k*32 + lane
    unsigned p2s[4], p2m[4];
#pragma unroll
    for (int k = 0; k < 4; k++) {
        int n = k * 32 + lane;
        int v = 0;
        bool valid = (n < 120);
        if (valid) {
            int p = 0;
#pragma unroll
            for (int i = 0; i < 16; i++)
                p += __popc((~(sp[i] ^ s1[n * 17 + i])) & sm[i]);
            v = 2 * p - M1;
        }
        p2s[k] = __ballot_sync(0xffffffffu, valid && (v > 0));
        p2m[k] = __ballot_sync(0xffffffffu, valid && (v != 0));
    }
    int M2 = __popc(p2m[0]) + __popc(p2m[1]) + __popc(p2m[2]) + __popc(p2m[3]);

    // fc2: 84 neurons
    unsigned p3s[3], p3m[3];
#pragma unroll
    for (int k = 0; k < 3; k++) {
        int n = k * 32 + lane;
        int v = 0;
        bool valid = (n < 84);
        if (valid) {
            int p = 0;
#pragma unroll
            for (int j = 0; j < 4; j++)
                p += __popc((~(p2s[j] ^ s2w[n * 5 + j])) & p2m[j]);
            v = 2 * p - M2;
        }
        p3s[k] = __ballot_sync(0xffffffffu, valid && (v > 0));
        p3m[k] = __ballot_sync(0xffffffffu, valid && (v != 0));
    }
    int M3 = __popc(p3m[0]) + __popc(p3m[1]) + __popc(p3m[2]);

    // fc3: 10 neurons
    if (lane < 10) {
        int p = 0;
#pragma unroll
        for (int j = 0; j < 3; j++)
            p += __popc((~(p3s[j] ^ s3w[lane * 3 + j])) & p3m[j]);
        out[b * 10 + lane] = (float)(2 * p - M3);
    }
}

// ---------------- launch ----------------
extern "C" void kernel_launch(void* const* d_in, const int* in_sizes, int n_in,
                              void* d_out, int out_size) {
    const float* x  = (const float*)d_in[0];
    const float* w1 = (const float*)d_in[1];
    const float* w2 = (const float*)d_in[2];
    const float* f1 = (const float*)d_in[3];
    const float* f2 = (const float*)d_in[4];
    const float* f3 = (const float*)d_in[5];
    float* out = (float*)d_out;

    int B = in_sizes[0] / 1024;
    if (B > B_MAX) B = B_MAX;

    pack_weights<<<8, 256>>>(w1, w2, f1, f2, f3);

    int nrows = B * 32;
    pack_x<<<(nrows * 32 + 255) / 256, 256>>>(x, nrows);

    conv1_k<<<(B * 14 + 255) / 256, 256>>>(B);

    conv2_k<<<(B * 25 + 255) / 256, 256>>>(B);

    fc_k<<<(B + 7) / 8, 256>>>(out, B);
}

// round 4
// speedup vs baseline: 2.5884x; 1.2876x over previous
#include <cuda_runtime.h>
#include <stdint.h>

#define B_MAX 16384

// ---------------- scratch (device globals; no allocation) ----------------
__device__ unsigned g_xbits[B_MAX * 32];           // [b][y] 32 sign bits per row
__device__ unsigned g_c1bits[B_MAX * 14 * 6];      // [b][row][ic] 14-bit rows after conv1+pool
__device__ unsigned g_s2[B_MAX * 25];              // [b][cell]: pos bits 0-15, mask bits 16-31
__device__ unsigned g_wp1[8];                      // conv1 weight sign bits (25 per oc), padded
__device__ unsigned g_wp2[16 * 8];                 // conv2 weights packed 150b -> 5 words, pad 8
__device__ unsigned g_fw1[120 * 16];               // fc1: 25-bit word per (n, oc)
__device__ unsigned g_fw2[84 * 4];                 // fc2: 120 bits -> 4 words per n
__device__ unsigned g_fw3[10 * 3];                 // fc3: 84 bits -> 3 words per n

// ---------------- K0: pack all weights into sign bitmasks ----------------
__global__ void pack_weights(const float* __restrict__ w1, const float* __restrict__ w2,
                             const float* __restrict__ f1, const float* __restrict__ f2,
                             const float* __restrict__ f3) {
    int t = blockIdx.x * blockDim.x + threadIdx.x;
    int stride = blockDim.x * gridDim.x;

    if (t < 8) {
        unsigned v = 0;
        if (t < 6)
            for (int i = 0; i < 25; i++) v |= (unsigned)(w1[t * 25 + i] > 0.f) << i;
        g_wp1[t] = v;
    }
    if (t < 16) {  // oc: pack 6x25 bits -> 5x32-bit dense words
        unsigned wi[6];
        for (int ic = 0; ic < 6; ic++) {
            unsigned v = 0;
            for (int i = 0; i < 25; i++) v |= (unsigned)(w2[(t * 6 + ic) * 25 + i] > 0.f) << i;
            wi[ic] = v;
        }
        g_wp2[t * 8 + 0] = wi[0] | (wi[1] << 25);
        g_wp2[t * 8 + 1] = (wi[1] >> 7) | (wi[2] << 18);
        g_wp2[t * 8 + 2] = (wi[2] >> 14) | (wi[3] << 11);
        g_wp2[t * 8 + 3] = (wi[3] >> 21) | (wi[4] << 4) | (wi[5] << 29);
        g_wp2[t * 8 + 4] = (wi[5] >> 3);
        g_wp2[t * 8 + 5] = 0; g_wp2[t * 8 + 6] = 0; g_wp2[t * 8 + 7] = 0;
    }
    for (int w = t; w < 120 * 16; w += stride) {   // (n, oc) -> 25 bits
        int n = w >> 4, oc = w & 15;
        unsigned v = 0;
        for (int i = 0; i < 25; i++) v |= (unsigned)(f1[n * 400 + oc * 25 + i] > 0.f) << i;
        g_fw1[w] = v;
    }
    for (int w = t; w < 84 * 4; w += stride) {     // (n, j) -> bits j*32+k of 120
        int n = w >> 2, j = w & 3;
        unsigned v = 0;
        for (int k = 0; k < 32; k++) {
            int i = j * 32 + k;
            if (i < 120) v |= (unsigned)(f2[n * 120 + i] > 0.f) << k;
        }
        g_fw2[w] = v;
    }
    for (int w = t; w < 10 * 3; w += stride) {     // (n, j) -> bits j*32+k of 84
        int n = w / 3, j = w % 3;
        unsigned v = 0;
        for (int k = 0; k < 32; k++) {
            int i = j * 32 + k;
            if (i < 84) v |= (unsigned)(f3[n * 84 + i] > 0.f) << k;
        }
        g_fw3[w] = v;
    }
}

// ---------------- K1: pack x signs, one warp per 4 rows -------------------
__global__ void __launch_bounds__(256) pack_x(const float* __restrict__ x, int ngroups) {
    int g = (blockIdx.x * blockDim.x + threadIdx.x) >> 5;
    int lane = threadIdx.x & 31;
    if (g >= ngroups) return;
    const float* p = x + (size_t)g * 128 + lane;
    float v0 = p[0], v1 = p[32], v2 = p[64], v3 = p[96];
    unsigned b0 = __ballot_sync(0xffffffffu, v0 > 0.f);
    unsigned b1 = __ballot_sync(0xffffffffu, v1 > 0.f);
    unsigned b2 = __ballot_sync(0xffffffffu, v2 > 0.f);
    unsigned b3 = __ballot_sync(0xffffffffu, v3 > 0.f);
    if (lane == 0) *(uint4*)&g_xbits[g * 4] = make_uint4(b0, b1, b2, b3);
}

// ---------------- K2: conv1 + maxpool + binarize (fused) -----------------
// dot = 25 - 2*popc ; >0 <=> popc <= 12 ; conv1 outputs odd => never 0
__global__ void __launch_bounds__(256, 6) conv1_k(int B) {
    int t = blockIdx.x * blockDim.x + threadIdx.x;
    if (t >= B * 14) return;
    int b = t / 14, py = t % 14;

    unsigned r[6];
#pragma unroll
    for (int k = 0; k < 6; k++) r[k] = g_xbits[b * 32 + 2 * py + k];
    unsigned w[6];
#pragma unroll
    for (int oc = 0; oc < 6; oc++) w[oc] = g_wp1[oc];

    unsigned out[6] = {0, 0, 0, 0, 0, 0};
#pragma unroll
    for (int ox = 0; ox < 28; ox++) {
        unsigned win0 = 0;
#pragma unroll
        for (int j = 0; j < 5; j++) win0 |= ((r[j] >> ox) & 31u) << (5 * j);
        unsigned win1 = (win0 >> 5) | (((r[5] >> ox) & 31u) << 20);
        unsigned bit = 1u << (ox >> 1);
#pragma unroll
        for (int oc = 0; oc < 6; oc++) {
            int m = min(__popc(win0 ^ w[oc]), __popc(win1 ^ w[oc]));
            if (m <= 12) out[oc] |= bit;
        }
    }
    uint2* dst = (uint2*)&g_c1bits[(b * 14 + py) * 6];
    dst[0] = make_uint2(out[0], out[1]);
    dst[1] = make_uint2(out[2], out[3]);
    dst[2] = make_uint2(out[4], out[5]);
}

// ---------------- K3: conv2 + maxpool + ternarize (fused) ----------------
// thread = one pooled output cell (b, py, px); windows packed 150b -> 5 words,
// built progressively per ic-pair to keep register pressure low.
__global__ void __launch_bounds__(256, 6) conv2_k(int B) {
    __shared__ uint4 sw4[16][2];
    if (threadIdx.x < 32) {
        int oc = threadIdx.x >> 1, h = threadIdx.x & 1;
        sw4[oc][h] = ((const uint4*)&g_wp2[oc * 8])[h];
    }
    __syncthreads();

    int t = blockIdx.x * blockDim.x + threadIdx.x;
    if (t >= B * 25) return;
    int b = t / 25;
    int cell = t % 25;
    int py = cell / 5, px = cell % 5;
    int ox0 = 2 * px;

    const unsigned* base = &g_c1bits[(b * 14 + 2 * py) * 6];

    unsigned wpk[4][5];  // [q = cr*2 + h][word]
#pragma unroll
    for (int q = 0; q < 4; q++)
#pragma unroll
        for (int w = 0; w < 5; w++) wpk[q][w] = 0u;

#pragma unroll
    for (int icp = 0; icp < 3; icp++) {     // ic pair (2icp, 2icp+1)
        unsigned ra[6], rb[6];
#pragma unroll
        for (int k = 0; k < 6; k++) {
            uint2 v = *(const uint2*)&base[k * 6 + icp * 2];
            ra[k] = v.x; rb[k] = v.y;
        }
#pragma unroll
        for (int h = 0; h < 2; h++) {
            int ox = ox0 + h;
            unsigned va0 = 0, vb0 = 0;
#pragma unroll
            for (int j = 0; j < 5; j++) {
                va0 |= ((ra[j] >> ox) & 31u) << (5 * j);
                vb0 |= ((rb[j] >> ox) & 31u) << (5 * j);
            }
            unsigned va1 = (va0 >> 5) | (((ra[5] >> ox) & 31u) << 20);
            unsigned vb1 = (vb0 >> 5) | (((rb[5] >> ox) & 31u) << 20);
            if (icp == 0) {        // ic0 -> w0 ; ic1 -> w0(<<25), w1(>>7)
                wpk[h][0]     |= va0 | (vb0 << 25);
                wpk[h][1]     |= vb0 >> 7;
                wpk[2 + h][0] |= va1 | (vb1 << 25);
                wpk[2 + h][1] |= vb1 >> 7;
            } else if (icp == 1) { // ic2 -> w1(<<18), w2(>>14) ; ic3 -> w2(<<11), w3(>>21)
                wpk[h][1]     |= va0 << 18;
                wpk[h][2]     |= (va0 >> 14) | (vb0 << 11);
                wpk[h][3]     |= vb0 >> 21;
                wpk[2 + h][1] |= va1 << 18;
                wpk[2 + h][2] |= (va1 >> 14) | (vb1 << 11);
                wpk[2 + h][3] |= vb1 >> 21;
            } else {               // ic4 -> w3(<<4) ; ic5 -> w3(<<29), w4(>>3)
                wpk[h][3]     |= (va0 << 4) | (vb0 << 29);
                wpk[h][4]     |= vb0 >> 3;
                wpk[2 + h][3] |= (va1 << 4) | (vb1 << 29);
                wpk[2 + h][4] |= vb1 >> 3;
            }
        }
    }

    unsigned word = 0;
#pragma unroll
    for (int oc = 0; oc < 16; oc++) {
        uint4 wa = sw4[oc][0];
        unsigned w4v = sw4[oc][1].x;
        int d0 = __popc(wpk[0][0] ^ wa.x) + __popc(wpk[0][1] ^ wa.y)
               + __popc(wpk[0][2] ^ wa.z) + __popc(wpk[0][3] ^ wa.w)
               + __popc(wpk[0][4] ^ w4v);
        int d1 = __popc(wpk[1][0] ^ wa.x) + __popc(wpk[1][1] ^ wa.y)
               + __popc(wpk[1][2] ^ wa.z) + __popc(wpk[1][3] ^ wa.w)
               + __popc(wpk[1][4] ^ w4v);
        int d2 = __popc(wpk[2][0] ^ wa.x) + __popc(wpk[2][1] ^ wa.y)
               + __popc(wpk[2][2] ^ wa.z) + __popc(wpk[2][3] ^ wa.w)
               + __popc(wpk[2][4] ^ w4v);
        int d3 = __popc(wpk[3][0] ^ wa.x) + __popc(wpk[3][1] ^ wa.y)
               + __popc(wpk[3][2] ^ wa.z) + __popc(wpk[3][3] ^ wa.w)
               + __popc(wpk[3][4] ^ w4v);
        int m = min(min(d0, d1), min(d2, d3));
        if (m <= 74) word |= 1u << oc;          // pooled value > 0
        if (m != 75) word |= 1u << (16 + oc);   // pooled value != 0
    }
    g_s2[b * 25 + cell] = word;
}

// ---------------- K4: fc1 -> fc2 -> fc3 fused, one warp per image --------
__global__ void fc_k(float* __restrict__ out, int B) {
    __shared__ unsigned s1[120 * 17];
    __shared__ unsigned s2w[84 * 5];
    __shared__ unsigned s3w[30];
    int tid = threadIdx.x;
    for (int i = tid; i < 120 * 16; i += 256) s1[(i >> 4) * 17 + (i & 15)] = g_fw1[i];
    for (int i = tid; i < 84 * 4; i += 256) s2w[(i >> 2) * 5 + (i & 3)] = g_fw2[i];
    if (tid < 30) s3w[tid] = g_fw3[tid];
    __syncthreads();

    int warp = blockIdx.x * 8 + (tid >> 5);
    int lane = tid & 31;
    if (warp >= B) return;
    int b = warp;

    unsigned W = (lane < 25) ? g_s2[b * 25 + lane] : 0u;
    unsigned sp[16], sm[16];
#pragma unroll
    for (int oc = 0; oc < 16; oc++) {
        sp[oc] = __ballot_sync(0xffffffffu, (W >> oc) & 1u);
        sm[oc] = __ballot_sync(0xffffffffu, (W >> (16 + oc)) & 1u);
    }
    int M1 = 0;
#pragma unroll
    for (int i = 0; i < 16; i++) M1 += __popc(sm[i]);

    unsigned p2s[4], p2m[4];
#pragma unroll
    for (int k = 0; k < 4; k++) {
        int n = k * 32 + lane;
        int v = 0;
        bool valid = (n < 120);
        if (valid) {
            int p = 0;
#pragma unroll
            for (int i = 0; i < 16; i++)
                p += __popc((~(sp[i] ^ s1[n * 17 + i])) & sm[i]);
            v = 2 * p - M1;
        }
        p2s[k] = __ballot_sync(0xffffffffu, valid && (v > 0));
        p2m[k] = __ballot_sync(0xffffffffu, valid && (v != 0));
    }
    int M2 = __popc(p2m[0]) + __popc(p2m[1]) + __popc(p2m[2]) + __popc(p2m[3]);

    unsigned p3s[3], p3m[3];
#pragma unroll
    for (int k = 0; k < 3; k++) {
        int n = k * 32 + lane;
        int v = 0;
        bool valid = (n < 84);
        if (valid) {
            int p = 0;
#pragma unroll
            for (int j = 0; j < 4; j++)
                p += __popc((~(p2s[j] ^ s2w[n * 5 + j])) & p2m[j]);
            v = 2 * p - M2;
        }
        p3s[k] = __ballot_sync(0xffffffffu, valid && (v > 0));
        p3m[k] = __ballot_sync(0xffffffffu, valid && (v != 0));
    }
    int M3 = __popc(p3m[0]) + __popc(p3m[1]) + __popc(p3m[2]);

    if (lane < 10) {
        int p = 0;
#pragma unroll
        for (int j = 0; j < 3; j++)
            p += __popc((~(p3s[j] ^ s3w[lane * 3 + j])) & p3m[j]);
        out[b * 10 + lane] = (float)(2 * p - M3);
    }
}

// ---------------- launch ----------------
extern "C" void kernel_launch(void* const* d_in, const int* in_sizes, int n_in,
                              void* d_out, int out_size) {
    const float* x  = (const float*)d_in[0];
    const float* w1 = (const float*)d_in[1];
    const float* w2 = (const float*)d_in[2];
    const float* f1 = (const float*)d_in[3];
    const float* f2 = (const float*)d_in[4];
    const float* f3 = (const float*)d_in[5];
    float* out = (float*)d_out;

    int B = in_sizes[0] / 1024;
    if (B > B_MAX) B = B_MAX;

    pack_weights<<<8, 256>>>(w1, w2, f1, f2, f3);

    int ngroups = B * 8;  // 4 rows per warp
    pack_x<<<(ngroups * 32 + 255) / 256, 256>>>(x, ngroups);

    conv1_k<<<(B * 14 + 255) / 256, 256>>>(B);

    conv2_k<<<(B * 25 + 255) / 256, 256>>>(B);

    fc_k<<<(B + 7) / 8, 256>>>(out, B);
}